// round 14
// baseline (speedup 1.0000x reference)
#include <cuda_runtime.h>
#include <cuda_bf16.h>
#include <cuda_fp16.h>
#include <cstdint>

#define NN      8192
#define F_IN    512
#define NOUT    64
#define LRA     0.2f
#define L2E     1.4426950408889634f
#define JSPLITS 4
#define JLEN    (NN / JSPLITS)     // 2048
#define NCH     (JLEN / 16)        // 128 chunks of k=16
#define NBLK    (NCH / 2)          // 64 blocks of k=32
#define BST     80
#define BBUF    (64 * BST)         // 5120 B per B stage
#define ABUF    16384              // 16 KB adj per stage (128 rows x 32 ints)
// dynamic smem layout
#define SM_E2   0                  // 8192 B
#define SM_B    8192               // 3 x 5120
#define SM_ADJ  (8192 + 3 * BBUF)  // 3 x 16384
#define SM_TOT  (SM_ADJ + 3 * ABUF)

// ---------------- device scratch (no cudaMalloc allowed) -------------------
__device__ uint4 g_W_pk[64 * 32 * 4];
__device__ __align__(16) __half g_WhT_hi[NOUT * NN];
__device__ float g_e1[NN];
__device__ float g_e2[NN];
__device__ float g_m2;
__device__ float g_pacc[JSPLITS][NN][NOUT];
__device__ float g_pden[JSPLITS][NN];
__device__ int   g_cnt[64];

// ---------------- helpers ---------------------------------------------------
__device__ __forceinline__ void mma_bf16(float* d, const unsigned* a,
                                         unsigned b0, unsigned b1) {
    asm volatile(
        "mma.sync.aligned.m16n8k16.row.col.f32.bf16.bf16.f32 "
        "{%0,%1,%2,%3}, {%4,%5,%6,%7}, {%8,%9}, {%0,%1,%2,%3};"
        : "+f"(d[0]), "+f"(d[1]), "+f"(d[2]), "+f"(d[3])
        : "r"(a[0]), "r"(a[1]), "r"(a[2]), "r"(a[3]), "r"(b0), "r"(b1));
}
__device__ __forceinline__ void mma_f16(float* d, const unsigned* a,
                                        unsigned b0, unsigned b1) {
    asm volatile(
        "mma.sync.aligned.m16n8k16.row.col.f32.f16.f16.f32 "
        "{%0,%1,%2,%3}, {%4,%5,%6,%7}, {%8,%9}, {%0,%1,%2,%3};"
        : "+f"(d[0]), "+f"(d[1]), "+f"(d[2]), "+f"(d[3])
        : "r"(a[0]), "r"(a[1]), "r"(a[2]), "r"(a[3]), "r"(b0), "r"(b1));
}
__device__ __forceinline__ void ldsm4(unsigned* r, uint32_t addr) {
    asm volatile("ldmatrix.sync.aligned.m8n8.x4.shared.b16 {%0,%1,%2,%3}, [%4];"
                 : "=r"(r[0]), "=r"(r[1]), "=r"(r[2]), "=r"(r[3]) : "r"(addr));
}
__device__ __forceinline__ int2 lds64(uint32_t a) {
    int2 v;
    asm volatile("ld.shared.v2.u32 {%0,%1}, [%2];" : "=r"(v.x), "=r"(v.y) : "r"(a));
    return v;
}
__device__ __forceinline__ unsigned cvt2b(float po, float pe) {
    unsigned r;
    asm("cvt.rn.bf16x2.f32 %0, %1, %2;" : "=r"(r) : "f"(po), "f"(pe));
    return r;
}
__device__ __forceinline__ unsigned cvt2h(float po, float pe) {
    unsigned r;
    asm("cvt.rn.f16x2.f32 %0, %1, %2;" : "=r"(r) : "f"(po), "f"(pe));
    return r;
}
__device__ __forceinline__ float ex2a(float x) {
    float r;
    asm("ex2.approx.ftz.f32 %0, %1;" : "=f"(r) : "f"(x));
    return r;
}
__device__ __forceinline__ float bfhf(float x) {
    return __bfloat162float(__float2bfloat16_rn(x));
}
__device__ __forceinline__ uint32_t smem_u32(const void* p) {
    return (uint32_t)__cvta_generic_to_shared(p);
}
__device__ __forceinline__ void cpa16(uint32_t dst, const void* src) {
    asm volatile("cp.async.cg.shared.global [%0], [%1], 16;" :: "r"(dst), "l"(src));
}
__device__ __forceinline__ void cpcommit() {
    asm volatile("cp.async.commit_group;" ::: "memory");
}
template <int N> __device__ __forceinline__ void cpwait() {
    asm volatile("cp.async.wait_group %0;" :: "n"(N) : "memory");
}

// ---------------------------------------------------------------------------
// Kernel 0: pack W into bf16 hi/lo fragment layout.
// ---------------------------------------------------------------------------
__global__ void __launch_bounds__(256) prep_w(const float* __restrict__ W) {
    const int t = blockIdx.x * 256 + threadIdx.x;
    const int s = t & 3, kc = (t >> 2) & 31, n = t >> 7;
    const int k0 = kc * 16 + 2 * s;
    float v00 = W[(k0 + 0) * 64 + n], v01 = W[(k0 + 1) * 64 + n];
    float v10 = W[(k0 + 8) * 64 + n], v11 = W[(k0 + 9) * 64 + n];
    float h00 = bfhf(v00), h01 = bfhf(v01), h10 = bfhf(v10), h11 = bfhf(v11);
    uint4 o;
    o.x = cvt2b(h01, h00);
    o.y = cvt2b(h11, h10);
    o.z = cvt2b(v01 - h01, v00 - h00);
    o.w = cvt2b(v11 - h11, v10 - h10);
    g_W_pk[(n * 32 + kc) * 4 + s] = o;
}

// ---------------------------------------------------------------------------
// Kernel 1: Wh = h @ W via mma.sync (3-product bf16 split). (R12 structure)
// ---------------------------------------------------------------------------
__global__ void __launch_bounds__(256, 1) wh_mma(const float* __restrict__ h,
                                                 const float* __restrict__ a) {
    __shared__ float s_h[3][64][20];
    __shared__ float s_t[64][65];
    __shared__ float s_e1p[8][16];
    __shared__ float s_e2p[8][16];

    const int tid = threadIdx.x;
    const int w = tid >> 5;
    const int l = tid & 31;
    const int wg = w >> 1;
    const int half = w & 1;
    const int r = l >> 2;
    const int c = (l & 3) * 2;
    const int node0 = blockIdx.x * 64;

    const uint32_t shb = smem_u32(&s_h[0][0][0]);
    auto stage = [&](int kc, int s) {
        const int row = tid >> 2, q4 = tid & 3;
        const float* src = h + (size_t)(node0 + row) * F_IN + kc * 16 + q4 * 4;
        cpa16(shb + (uint32_t)((s * 64 + row) * 20 + q4 * 4) * 4, src);
    };

    stage(0, 0); cpcommit();
    stage(1, 1); cpcommit();

    float acc[4][4];
#pragma unroll
    for (int n = 0; n < 4; ++n)
#pragma unroll
        for (int q = 0; q < 4; ++q) acc[n][q] = 0.f;

    const uint4* __restrict__ wpk = g_W_pk;

    for (int kc = 0; kc < 32; ++kc) {
        const int ss = kc % 3;
        if (kc + 1 < 32) cpwait<1>(); else cpwait<0>();
        __syncthreads();
        if (kc + 2 < 32) { stage(kc + 2, (kc + 2) % 3); cpcommit(); }

        uint4 B4[4];
#pragma unroll
        for (int nt = 0; nt < 4; ++nt)
            B4[nt] = wpk[(((half * 4 + nt) * 8 + r) * 32 + kc) * 4 + (l & 3)];

        float2 v0 = *(const float2*)&s_h[ss][wg * 16 + r][c];
        float2 v1 = *(const float2*)&s_h[ss][wg * 16 + r + 8][c];
        float2 v2 = *(const float2*)&s_h[ss][wg * 16 + r][c + 8];
        float2 v3 = *(const float2*)&s_h[ss][wg * 16 + r + 8][c + 8];
        float h0x = bfhf(v0.x), h0y = bfhf(v0.y);
        float h1x = bfhf(v1.x), h1y = bfhf(v1.y);
        float h2x = bfhf(v2.x), h2y = bfhf(v2.y);
        float h3x = bfhf(v3.x), h3y = bfhf(v3.y);
        unsigned Ah[4], Al[4];
        Ah[0] = cvt2b(h0y, h0x); Al[0] = cvt2b(v0.y - h0y, v0.x - h0x);
        Ah[1] = cvt2b(h1y, h1x); Al[1] = cvt2b(v1.y - h1y, v1.x - h1x);
        Ah[2] = cvt2b(h2y, h2x); Al[2] = cvt2b(v2.y - h2y, v2.x - h2x);
        Ah[3] = cvt2b(h3y, h3x); Al[3] = cvt2b(v3.y - h3y, v3.x - h3x);

#pragma unroll
        for (int nt = 0; nt < 4; ++nt) mma_bf16(acc[nt], Ah, B4[nt].x, B4[nt].y);
#pragma unroll
        for (int nt = 0; nt < 4; ++nt) mma_bf16(acc[nt], Al, B4[nt].x, B4[nt].y);
#pragma unroll
        for (int nt = 0; nt < 4; ++nt) mma_bf16(acc[nt], Ah, B4[nt].z, B4[nt].w);
    }

    {
        float e1p0 = 0.f, e1p8 = 0.f, e2p0 = 0.f, e2p8 = 0.f;
#pragma unroll
        for (int nt = 0; nt < 4; ++nt) {
            const int col = half * 32 + nt * 8 + c;
            float2 a1v = *(const float2*)&a[col];
            float2 a2v = *(const float2*)&a[NOUT + col];
            e1p0 += acc[nt][0] * a1v.x + acc[nt][1] * a1v.y;
            e1p8 += acc[nt][2] * a1v.x + acc[nt][3] * a1v.y;
            e2p0 += acc[nt][0] * a2v.x + acc[nt][1] * a2v.y;
            e2p8 += acc[nt][2] * a2v.x + acc[nt][3] * a2v.y;
        }
#pragma unroll
        for (int off = 1; off <= 2; off <<= 1) {
            e1p0 += __shfl_xor_sync(0xffffffffu, e1p0, off);
            e1p8 += __shfl_xor_sync(0xffffffffu, e1p8, off);
            e2p0 += __shfl_xor_sync(0xffffffffu, e2p0, off);
            e2p8 += __shfl_xor_sync(0xffffffffu, e2p8, off);
        }
        if ((l & 3) == 0) {
            s_e1p[w][r] = e1p0; s_e1p[w][r + 8] = e1p8;
            s_e2p[w][r] = e2p0; s_e2p[w][r + 8] = e2p8;
        }
    }

#pragma unroll
    for (int nt = 0; nt < 4; ++nt) {
        const int cb = half * 32 + nt * 8 + c;
        s_t[wg * 16 + r][cb]         = acc[nt][0];
        s_t[wg * 16 + r][cb + 1]     = acc[nt][1];
        s_t[wg * 16 + r + 8][cb]     = acc[nt][2];
        s_t[wg * 16 + r + 8][cb + 1] = acc[nt][3];
    }
    __syncthreads();

    if (tid < 64) {
        const int wg2 = tid >> 4, rr = tid & 15;
        g_e1[node0 + wg2 * 16 + rr] = s_e1p[2 * wg2][rr] + s_e1p[2 * wg2 + 1][rr];
        g_e2[node0 + wg2 * 16 + rr] = s_e2p[2 * wg2][rr] + s_e2p[2 * wg2 + 1][rr];
    }

    {
        const int col = tid >> 2, nh = tid & 3;
        float f[16];
#pragma unroll
        for (int j = 0; j < 16; ++j) f[j] = s_t[nh * 16 + j][col];
        unsigned hw[8];
#pragma unroll
        for (int q = 0; q < 8; ++q) hw[q] = cvt2h(f[2 * q + 1], f[2 * q]);
        uint4* dh = (uint4*)(g_WhT_hi + (size_t)col * NN + blockIdx.x * 64 + nh * 16);
        dh[0] = *(uint4*)&hw[0];
        dh[1] = *(uint4*)&hw[4];
    }
}

// ---------------------------------------------------------------------------
// Kernel 1.5: global max of e2 (single CTA) + reset combine counters.
// ---------------------------------------------------------------------------
__global__ void __launch_bounds__(256) e2max_kernel() {
    __shared__ float sm[8];
    const int tid = threadIdx.x;
    if (tid < 64) g_cnt[tid] = 0;
    float m = -1e30f;
    for (int k = tid; k < NN; k += 256) m = fmaxf(m, g_e2[k]);
#pragma unroll
    for (int off = 16; off; off >>= 1)
        m = fmaxf(m, __shfl_xor_sync(0xffffffffu, m, off));
    if ((tid & 31) == 0) sm[tid >> 5] = m;
    __syncthreads();
    if (tid == 0) {
        float mm = sm[0];
#pragma unroll
        for (int q = 1; q < 8; ++q) mm = fmaxf(mm, sm[q]);
        g_m2 = mm;
    }
}

// ---------------------------------------------------------------------------
// Kernel 2: fused masked-exp + fp16 GEMM + ones-GEMM den + fused combine.
// NEW: adj staged through the 3-stage cp.async pipeline (coalesced, async,
// col-group smem layout matching fragment slots -> LDS.64 reads, no DRAM
// scoreboard in the loop); JSPLITS=4 -> grid 256 = ONE wave at occ 2.
// ---------------------------------------------------------------------------
__global__ void __launch_bounds__(256, 2) attn_kernel(const int* __restrict__ adj,
                                                      float* __restrict__ out) {
    extern __shared__ char dsm[];
    __shared__ int s_last;

    const int tid = threadIdx.x;
    const int w = tid >> 5;
    const int l = tid & 31;
    const int i0 = (int)(blockIdx.x >> 2) * 128;
    const int split = blockIdx.x & 3;
    const int j0 = split * JLEN;

    float* s_e2 = (float*)(dsm + SM_E2);
    {
        float4* d = (float4*)s_e2;
        const float4* s = (const float4*)(g_e2 + j0);
        for (int k = tid; k < JLEN / 4; k += 256) {
            float4 v = s[k];
            v.x *= L2E; v.y *= L2E; v.z *= L2E; v.w *= L2E;
            d[k] = v;
        }
    }

    const int rq = l >> 2;
    const int cqi = l & 3;
    const int cq = cqi * 2;
    const float M2s = g_m2 * L2E;

    float e1r[2], mi[2];
#pragma unroll
    for (int k = 0; k < 2; ++k) {
        int row = i0 + w * 16 + 8 * k + rq;
        e1r[k] = g_e1[row] * L2E;
        float mv = e1r[k] + M2s;
        mi[k] = mv > 0.f ? mv : LRA * mv;
    }

    const uint32_t sBs = smem_u32(dsm + SM_B);
    const uint32_t sAs = smem_u32(dsm + SM_ADJ);

    // combined B + adj staging for block blk into stage s
    auto stage = [&](int blk, int s) {
        // B: 64n x 32k fp16 = 4 KB
        const int cB = tid >> 6, nB = tid & 63;
        cpa16(sBs + (uint32_t)(s * BBUF + nB * BST + cB * 16),
              g_WhT_hi + (size_t)nB * NN + j0 + blk * 32 + cB * 8);
        // adj: 128 rows x 32 ints = 16 KB, col-group layout [g][row]
#pragma unroll
        for (int q = 0; q < 4; ++q) {
            const int idx = q * 256 + tid;
            const int row = idx >> 3, gc = idx & 7;
            cpa16(sAs + (uint32_t)(s * ABUF + gc * 2048 + row * 16),
                  adj + (size_t)(i0 + row) * NN + j0 + blk * 32 + gc * 4);
        }
    };

    const int g = l >> 3, lr = l & 7;
    const uint32_t sBm = sBs + (uint32_t)((lr + ((g >> 1) << 3)) * BST + ((g & 1) << 4));
    // adj per-lane base: group (cqi>>1), row (w*16+rq), byte-in-group (cqi&1)*8
    const uint32_t sAm = sAs + (uint32_t)(((cqi >> 1) * 2048) + ((w * 16 + rq) * 16) + ((cqi & 1) * 8));

    float acc[8][4];
#pragma unroll
    for (int n = 0; n < 8; ++n)
#pragma unroll
        for (int q = 0; q < 4; ++q) acc[n][q] = 0.f;
    float accd[4] = {0.f, 0.f, 0.f, 0.f};
    const unsigned ONES = 0x3C003C00u;

    stage(0, 0); cpcommit();
    stage(1, 1); cpcommit();

    for (int blk = 0; blk < NBLK; ++blk) {
        const int s = blk % 3;
        if (blk + 1 < NBLK) cpwait<1>(); else cpwait<0>();
        __syncthreads();
        if (blk + 2 < NBLK) { stage(blk + 2, (blk + 2) % 3); cpcommit(); }

#pragma unroll
        for (int c2 = 0; c2 < 2; ++c2) {
            const int ch = blk * 2 + c2;

            // ---- adj bits from smem (LDS.64, lat ~29) ----
            const uint32_t aoff = sAm + (uint32_t)(s * ABUF + c2 * 8192);
            int2 alo[2], ahi[2];
#pragma unroll
            for (int k = 0; k < 2; ++k) {
                alo[k] = lds64(aoff + k * 128);
                ahi[k] = lds64(aoff + 4096 + k * 128);
            }

            // ---- A fragments: shifted masked exp (base-2), fp16 ----
            const float* e2p = s_e2 + ch * 16;
            float2 e2a = *(const float2*)(e2p + cq);
            float2 e2b = *(const float2*)(e2p + cq + 8);
            unsigned Ah[4];
#pragma unroll
            for (int k = 0; k < 2; ++k) {
                const float e1v = e1r[k];
                float s0 = e1v + e2a.x; s0 = (s0 > 0.f ? s0 : LRA * s0) - mi[k];
                float s1 = e1v + e2a.y; s1 = (s1 > 0.f ? s1 : LRA * s1) - mi[k];
                float s2 = e1v + e2b.x; s2 = (s2 > 0.f ? s2 : LRA * s2) - mi[k];
                float s3 = e1v + e2b.y; s3 = (s3 > 0.f ? s3 : LRA * s3) - mi[k];
                float p0 = alo[k].x > 0 ? ex2a(s0) : 0.f;
                float p1 = alo[k].y > 0 ? ex2a(s1) : 0.f;
                float p2 = ahi[k].x > 0 ? ex2a(s2) : 0.f;
                float p3 = ahi[k].y > 0 ? ex2a(s3) : 0.f;
                Ah[k]     = cvt2h(p1, p0);
                Ah[k + 2] = cvt2h(p3, p2);
            }

            // ---- B fragments + products (+ ones-GEMM denominator) ----
            const uint32_t bo = (uint32_t)(s * BBUF + c2 * 32);
            unsigned Bh[8][2];
#pragma unroll
            for (int np = 0; np < 4; ++np)
                ldsm4(&Bh[2 * np][0], sBm + bo + np * (16 * BST));
#pragma unroll
            for (int n = 0; n < 8; ++n) mma_f16(acc[n], Ah, Bh[n][0], Bh[n][1]);
            mma_f16(accd, Ah, ONES, ONES);
        }
    }

    // ---- write partials ----
    if ((l & 3) == 0) {
        g_pden[split][i0 + w * 16 + rq]     = accd[0];
        g_pden[split][i0 + w * 16 + 8 + rq] = accd[2];
    }
    {
        const int row = i0 + w * 16 + rq;
#pragma unroll
        for (int n = 0; n < 8; ++n) {
            *(float2*)&g_pacc[split][row][n * 8 + cq]     = make_float2(acc[n][0], acc[n][1]);
            *(float2*)&g_pacc[split][row + 8][n * 8 + cq] = make_float2(acc[n][2], acc[n][3]);
        }
    }

    // ---- fused combine: last CTA of this row-tile reduces all splits ----
    __threadfence();
    __syncthreads();
    if (tid == 0)
        s_last = (atomicAdd(&g_cnt[blockIdx.x >> 2], 1) == JSPLITS - 1);
    __syncthreads();
    if (s_last) {
        __threadfence();
        for (int t = tid; t < 128 * 16; t += 256) {
            const int row = i0 + (t >> 4);
            const int c4 = (t & 15) * 4;
            float4 av = make_float4(0.f, 0.f, 0.f, 0.f);
            float den = 0.f;
#pragma unroll
            for (int sp = 0; sp < JSPLITS; ++sp) {
                float4 v = *(const float4*)&g_pacc[sp][row][c4];
                av.x += v.x; av.y += v.y; av.z += v.z; av.w += v.w;
                den += g_pden[sp][row];
            }
            if (den == 0.f) den = 1.f;
            float inv = 1.f / den;
            float4 o;
            o.x = av.x * inv; o.x = o.x > 0.f ? o.x : expm1f(o.x);
            o.y = av.y * inv; o.y = o.y > 0.f ? o.y : expm1f(o.y);
            o.z = av.z * inv; o.z = o.z > 0.f ? o.z : expm1f(o.z);
            o.w = av.w * inv; o.w = o.w > 0.f ? o.w : expm1f(o.w);
            *(float4*)&out[(size_t)row * NOUT + c4] = o;
        }
    }
}

// ---------------------------------------------------------------------------
extern "C" void kernel_launch(void* const* d_in, const int* in_sizes, int n_in,
                              void* d_out, int out_size) {
    const float* h   = (const float*)d_in[0];
    const float* W   = (const float*)d_in[1];
    const float* a   = (const float*)d_in[2];
    const int*   adj = (const int*)d_in[3];
    float* out = (float*)d_out;

    cudaFuncSetAttribute(attn_kernel, cudaFuncAttributeMaxDynamicSharedMemorySize, SM_TOT);
    prep_w<<<32, 256>>>(W);
    wh_mma<<<128, 256>>>(h, a);
    e2max_kernel<<<1, 256>>>();
    attn_kernel<<<(NN / 128) * JSPLITS, 256, SM_TOT>>>(adj, out);
}

// round 15
// speedup vs baseline: 1.5236x; 1.5236x over previous
#include <cuda_runtime.h>
#include <cuda_bf16.h>
#include <cuda_fp16.h>
#include <cstdint>

#define NN      8192
#define F_IN    512
#define NOUT    64
#define LRA     0.2f
#define L2E     1.4426950408889634f
#define JSPLITS 8
#define JLEN    (NN / JSPLITS)     // 1024
#define NCH     (JLEN / 16)        // 64 chunks of k=16
#define NBLK    (NCH / 2)          // 32 blocks of k=32
#define BST     80
#define BBUF    (64 * BST)

// ---------------- device scratch (no cudaMalloc allowed) -------------------
__device__ uint4 g_W_pk[64 * 32 * 4];
__device__ __align__(16) __half g_WhT_hi[NOUT * NN];   // j-PERMUTED within 16-groups
__device__ float g_e1[NN];
__device__ float g_e2[NN];
__device__ float g_m2;
__device__ float g_pacc[JSPLITS][NN][NOUT];
__device__ float g_pden[JSPLITS][NN];
__device__ int   g_cnt[64];

// ---------------- helpers ---------------------------------------------------
__device__ __forceinline__ void mma_bf16(float* d, const unsigned* a,
                                         unsigned b0, unsigned b1) {
    asm volatile(
        "mma.sync.aligned.m16n8k16.row.col.f32.bf16.bf16.f32 "
        "{%0,%1,%2,%3}, {%4,%5,%6,%7}, {%8,%9}, {%0,%1,%2,%3};"
        : "+f"(d[0]), "+f"(d[1]), "+f"(d[2]), "+f"(d[3])
        : "r"(a[0]), "r"(a[1]), "r"(a[2]), "r"(a[3]), "r"(b0), "r"(b1));
}
__device__ __forceinline__ void mma_f16(float* d, const unsigned* a,
                                        unsigned b0, unsigned b1) {
    asm volatile(
        "mma.sync.aligned.m16n8k16.row.col.f32.f16.f16.f32 "
        "{%0,%1,%2,%3}, {%4,%5,%6,%7}, {%8,%9}, {%0,%1,%2,%3};"
        : "+f"(d[0]), "+f"(d[1]), "+f"(d[2]), "+f"(d[3])
        : "r"(a[0]), "r"(a[1]), "r"(a[2]), "r"(a[3]), "r"(b0), "r"(b1));
}
__device__ __forceinline__ void ldsm4(unsigned* r, uint32_t addr) {
    asm volatile("ldmatrix.sync.aligned.m8n8.x4.shared.b16 {%0,%1,%2,%3}, [%4];"
                 : "=r"(r[0]), "=r"(r[1]), "=r"(r[2]), "=r"(r[3]) : "r"(addr));
}
__device__ __forceinline__ unsigned cvt2b(float po, float pe) {
    unsigned r;
    asm("cvt.rn.bf16x2.f32 %0, %1, %2;" : "=r"(r) : "f"(po), "f"(pe));
    return r;
}
__device__ __forceinline__ unsigned cvt2h(float po, float pe) {
    unsigned r;
    asm("cvt.rn.f16x2.f32 %0, %1, %2;" : "=r"(r) : "f"(po), "f"(pe));
    return r;
}
__device__ __forceinline__ float ex2a(float x) {
    float r;
    asm("ex2.approx.ftz.f32 %0, %1;" : "=f"(r) : "f"(x));
    return r;
}
__device__ __forceinline__ float bfhf(float x) {
    return __bfloat162float(__float2bfloat16_rn(x));
}
__device__ __forceinline__ uint32_t smem_u32(const void* p) {
    return (uint32_t)__cvta_generic_to_shared(p);
}
__device__ __forceinline__ void cpa16(uint32_t dst, const void* src) {
    asm volatile("cp.async.cg.shared.global [%0], [%1], 16;" :: "r"(dst), "l"(src));
}
__device__ __forceinline__ void cpcommit() {
    asm volatile("cp.async.commit_group;" ::: "memory");
}
template <int N> __device__ __forceinline__ void cpwait() {
    asm volatile("cp.async.wait_group %0;" :: "n"(N) : "memory");
}

// ---------------------------------------------------------------------------
// Kernel 0: pack W into bf16 hi/lo fragment layout.
// ---------------------------------------------------------------------------
__global__ void __launch_bounds__(256) prep_w(const float* __restrict__ W) {
    const int t = blockIdx.x * 256 + threadIdx.x;
    const int s = t & 3, kc = (t >> 2) & 31, n = t >> 7;
    const int k0 = kc * 16 + 2 * s;
    float v00 = W[(k0 + 0) * 64 + n], v01 = W[(k0 + 1) * 64 + n];
    float v10 = W[(k0 + 8) * 64 + n], v11 = W[(k0 + 9) * 64 + n];
    float h00 = bfhf(v00), h01 = bfhf(v01), h10 = bfhf(v10), h11 = bfhf(v11);
    uint4 o;
    o.x = cvt2b(h01, h00);
    o.y = cvt2b(h11, h10);
    o.z = cvt2b(v01 - h01, v00 - h00);
    o.w = cvt2b(v11 - h11, v10 - h10);
    g_W_pk[(n * 32 + kc) * 4 + s] = o;
}

// ---------------------------------------------------------------------------
// Kernel 1: Wh = h @ W via mma.sync (3-product bf16 split). (R12 structure)
// Epilogue pack PERMUTES j within each 16-group:
//   byte-pos 2c,2c+1   <- j 4c,4c+1
//   byte-pos 2c+8,2c+9 <- j 4c+2,4c+3
// so attn lane quad c owns contiguous j {4c..4c+3}.
// ---------------------------------------------------------------------------
__global__ void __launch_bounds__(256, 1) wh_mma(const float* __restrict__ h,
                                                 const float* __restrict__ a) {
    __shared__ float s_h[3][64][20];
    __shared__ float s_t[64][65];
    __shared__ float s_e1p[8][16];
    __shared__ float s_e2p[8][16];

    const int tid = threadIdx.x;
    const int w = tid >> 5;
    const int l = tid & 31;
    const int wg = w >> 1;
    const int half = w & 1;
    const int r = l >> 2;
    const int c = (l & 3) * 2;
    const int node0 = blockIdx.x * 64;

    const uint32_t shb = smem_u32(&s_h[0][0][0]);
    auto stage = [&](int kc, int s) {
        const int row = tid >> 2, q4 = tid & 3;
        const float* src = h + (size_t)(node0 + row) * F_IN + kc * 16 + q4 * 4;
        cpa16(shb + (uint32_t)((s * 64 + row) * 20 + q4 * 4) * 4, src);
    };

    stage(0, 0); cpcommit();
    stage(1, 1); cpcommit();

    float acc[4][4];
#pragma unroll
    for (int n = 0; n < 4; ++n)
#pragma unroll
        for (int q = 0; q < 4; ++q) acc[n][q] = 0.f;

    const uint4* __restrict__ wpk = g_W_pk;

    for (int kc = 0; kc < 32; ++kc) {
        const int ss = kc % 3;
        if (kc + 1 < 32) cpwait<1>(); else cpwait<0>();
        __syncthreads();
        if (kc + 2 < 32) { stage(kc + 2, (kc + 2) % 3); cpcommit(); }

        uint4 B4[4];
#pragma unroll
        for (int nt = 0; nt < 4; ++nt)
            B4[nt] = wpk[(((half * 4 + nt) * 8 + r) * 32 + kc) * 4 + (l & 3)];

        float2 v0 = *(const float2*)&s_h[ss][wg * 16 + r][c];
        float2 v1 = *(const float2*)&s_h[ss][wg * 16 + r + 8][c];
        float2 v2 = *(const float2*)&s_h[ss][wg * 16 + r][c + 8];
        float2 v3 = *(const float2*)&s_h[ss][wg * 16 + r + 8][c + 8];
        float h0x = bfhf(v0.x), h0y = bfhf(v0.y);
        float h1x = bfhf(v1.x), h1y = bfhf(v1.y);
        float h2x = bfhf(v2.x), h2y = bfhf(v2.y);
        float h3x = bfhf(v3.x), h3y = bfhf(v3.y);
        unsigned Ah[4], Al[4];
        Ah[0] = cvt2b(h0y, h0x); Al[0] = cvt2b(v0.y - h0y, v0.x - h0x);
        Ah[1] = cvt2b(h1y, h1x); Al[1] = cvt2b(v1.y - h1y, v1.x - h1x);
        Ah[2] = cvt2b(h2y, h2x); Al[2] = cvt2b(v2.y - h2y, v2.x - h2x);
        Ah[3] = cvt2b(h3y, h3x); Al[3] = cvt2b(v3.y - h3y, v3.x - h3x);

#pragma unroll
        for (int nt = 0; nt < 4; ++nt) mma_bf16(acc[nt], Ah, B4[nt].x, B4[nt].y);
#pragma unroll
        for (int nt = 0; nt < 4; ++nt) mma_bf16(acc[nt], Al, B4[nt].x, B4[nt].y);
#pragma unroll
        for (int nt = 0; nt < 4; ++nt) mma_bf16(acc[nt], Ah, B4[nt].z, B4[nt].w);
    }

    {
        float e1p0 = 0.f, e1p8 = 0.f, e2p0 = 0.f, e2p8 = 0.f;
#pragma unroll
        for (int nt = 0; nt < 4; ++nt) {
            const int col = half * 32 + nt * 8 + c;
            float2 a1v = *(const float2*)&a[col];
            float2 a2v = *(const float2*)&a[NOUT + col];
            e1p0 += acc[nt][0] * a1v.x + acc[nt][1] * a1v.y;
            e1p8 += acc[nt][2] * a1v.x + acc[nt][3] * a1v.y;
            e2p0 += acc[nt][0] * a2v.x + acc[nt][1] * a2v.y;
            e2p8 += acc[nt][2] * a2v.x + acc[nt][3] * a2v.y;
        }
#pragma unroll
        for (int off = 1; off <= 2; off <<= 1) {
            e1p0 += __shfl_xor_sync(0xffffffffu, e1p0, off);
            e1p8 += __shfl_xor_sync(0xffffffffu, e1p8, off);
            e2p0 += __shfl_xor_sync(0xffffffffu, e2p0, off);
            e2p8 += __shfl_xor_sync(0xffffffffu, e2p8, off);
        }
        if ((l & 3) == 0) {
            s_e1p[w][r] = e1p0; s_e1p[w][r + 8] = e1p8;
            s_e2p[w][r] = e2p0; s_e2p[w][r + 8] = e2p8;
        }
    }

#pragma unroll
    for (int nt = 0; nt < 4; ++nt) {
        const int cb = half * 32 + nt * 8 + c;
        s_t[wg * 16 + r][cb]         = acc[nt][0];
        s_t[wg * 16 + r][cb + 1]     = acc[nt][1];
        s_t[wg * 16 + r + 8][cb]     = acc[nt][2];
        s_t[wg * 16 + r + 8][cb + 1] = acc[nt][3];
    }
    __syncthreads();

    if (tid < 64) {
        const int wg2 = tid >> 4, rr = tid & 15;
        g_e1[node0 + wg2 * 16 + rr] = s_e1p[2 * wg2][rr] + s_e1p[2 * wg2 + 1][rr];
        g_e2[node0 + wg2 * 16 + rr] = s_e2p[2 * wg2][rr] + s_e2p[2 * wg2 + 1][rr];
    }

    // ---- pack WhT fp16 with j-permutation within the 16-group ----
    {
        const int col = tid >> 2, nh = tid & 3;
        float f[16];
#pragma unroll
        for (int j = 0; j < 16; ++j) f[j] = s_t[nh * 16 + j][col];
        unsigned hw[8];
#pragma unroll
        for (int q = 0; q < 4; ++q) {
            hw[q]     = cvt2h(f[4 * q + 1], f[4 * q]);       // byte-pos 2q,2q+1 <- j 4q,4q+1
            hw[4 + q] = cvt2h(f[4 * q + 3], f[4 * q + 2]);   // byte-pos 2q+8,.. <- j 4q+2,4q+3
        }
        uint4* dh = (uint4*)(g_WhT_hi + (size_t)col * NN + blockIdx.x * 64 + nh * 16);
        dh[0] = *(uint4*)&hw[0];
        dh[1] = *(uint4*)&hw[4];
    }
}

// ---------------------------------------------------------------------------
// Kernel 1.5: global max of e2 (single CTA) + reset combine counters.
// ---------------------------------------------------------------------------
__global__ void __launch_bounds__(256) e2max_kernel() {
    __shared__ float sm[8];
    const int tid = threadIdx.x;
    if (tid < 64) g_cnt[tid] = 0;
    float m = -1e30f;
    for (int k = tid; k < NN; k += 256) m = fmaxf(m, g_e2[k]);
#pragma unroll
    for (int off = 16; off; off >>= 1)
        m = fmaxf(m, __shfl_xor_sync(0xffffffffu, m, off));
    if ((tid & 31) == 0) sm[tid >> 5] = m;
    __syncthreads();
    if (tid == 0) {
        float mm = sm[0];
#pragma unroll
        for (int q = 1; q < 8; ++q) mm = fmaxf(mm, sm[q]);
        g_m2 = mm;
    }
}

// ---------------------------------------------------------------------------
// Kernel 2: fused masked-exp + fp16 GEMM + ones-GEMM den + fused combine.
// j-permuted fragments: lane quad c owns contiguous j {4c..4c+3}:
//   adj = ONE int4 LDG.128 per row per chunk (was 2x LDG.64),
//   e2  = one LDS.128. Depth-2 adj register pipeline retained (R13).
// ---------------------------------------------------------------------------
__global__ void __launch_bounds__(256, 2) attn_kernel(const int* __restrict__ adj,
                                                      float* __restrict__ out) {
    __shared__ float s_e2[JLEN];
    __shared__ __align__(16) char s_B[3][BBUF];
    __shared__ int s_last;

    const int tid = threadIdx.x;
    const int w = tid >> 5;
    const int l = tid & 31;
    const int i0 = (int)(blockIdx.x >> 3) * 128;
    const int split = blockIdx.x & 7;
    const int j0 = split * JLEN;

    {
        float4* d = (float4*)s_e2;
        const float4* s = (const float4*)(g_e2 + j0);
        for (int k = tid; k < JLEN / 4; k += 256) {
            float4 v = s[k];
            v.x *= L2E; v.y *= L2E; v.z *= L2E; v.w *= L2E;
            d[k] = v;
        }
    }

    const int rq = l >> 2;
    const int cqi = l & 3;
    const float M2s = g_m2 * L2E;

    float e1r[2], mi[2];
    const int* rb[2];
#pragma unroll
    for (int k = 0; k < 2; ++k) {
        int row = i0 + w * 16 + 8 * k + rq;
        e1r[k] = g_e1[row] * L2E;
        float mv = e1r[k] + M2s;
        mi[k] = mv > 0.f ? mv : LRA * mv;
        rb[k] = adj + (size_t)row * NN + j0 + 4 * cqi;   // contiguous 4-j group
    }

    const uint32_t sBs = smem_u32(&s_B[0][0]);
    auto stage = [&](int blk, int s) {
        const int c = tid >> 6;
        const int n = tid & 63;
        const __half* src = g_WhT_hi + (size_t)n * NN + j0 + blk * 32 + c * 8;
        cpa16(sBs + (uint32_t)(s * BBUF + n * BST + c * 16), src);
    };

    const int g = l >> 3, lr = l & 7;
    const uint32_t sBm = sBs + (uint32_t)((lr + ((g >> 1) << 3)) * BST + ((g & 1) << 4));

    float acc[8][4];
#pragma unroll
    for (int n = 0; n < 8; ++n)
#pragma unroll
        for (int q = 0; q < 4; ++q) acc[n][q] = 0.f;
    float accd[4] = {0.f, 0.f, 0.f, 0.f};
    const unsigned ONES = 0x3C003C00u;

    // depth-2 adj register pipeline: one int4 per row per chunk
    int4 av[2][2];
    auto loadAdj = [&](int ch) {
        const int b = ch & 1;
#pragma unroll
        for (int k = 0; k < 2; ++k)
            av[b][k] = *(const int4*)(rb[k] + ch * 16);
    };

    stage(0, 0); cpcommit();
    stage(1, 1); cpcommit();
    loadAdj(0);
    loadAdj(1);

    for (int blk = 0; blk < NBLK; ++blk) {
        const int s = blk % 3;
        if (blk + 1 < NBLK) cpwait<1>(); else cpwait<0>();
        __syncthreads();
        if (blk + 2 < NBLK) { stage(blk + 2, (blk + 2) % 3); cpcommit(); }

#pragma unroll
        for (int c2 = 0; c2 < 2; ++c2) {
            const int ch = blk * 2 + c2;
            const int b = ch & 1;

            // ---- A fragments: shifted masked exp (base-2), fp16 ----
            const float4 e2v = *(const float4*)(s_e2 + ch * 16 + 4 * cqi);
            unsigned Ah[4];
#pragma unroll
            for (int k = 0; k < 2; ++k) {
                const float e1v = e1r[k];
                float s0 = e1v + e2v.x; s0 = (s0 > 0.f ? s0 : LRA * s0) - mi[k];
                float s1 = e1v + e2v.y; s1 = (s1 > 0.f ? s1 : LRA * s1) - mi[k];
                float s2 = e1v + e2v.z; s2 = (s2 > 0.f ? s2 : LRA * s2) - mi[k];
                float s3 = e1v + e2v.w; s3 = (s3 > 0.f ? s3 : LRA * s3) - mi[k];
                float p0 = av[b][k].x > 0 ? ex2a(s0) : 0.f;
                float p1 = av[b][k].y > 0 ? ex2a(s1) : 0.f;
                float p2 = av[b][k].z > 0 ? ex2a(s2) : 0.f;
                float p3 = av[b][k].w > 0 ? ex2a(s3) : 0.f;
                Ah[k]     = cvt2h(p1, p0);   // hw k-lo pair  = j 4c,4c+1
                Ah[k + 2] = cvt2h(p3, p2);   // hw k-hi pair  = j 4c+2,4c+3
            }

            // ---- refill this buffer for chunk ch+2 ----
            if (ch + 2 < NCH) loadAdj(ch + 2);

            // ---- B fragments + products (+ ones-GEMM denominator) ----
            const uint32_t bo = (uint32_t)(s * BBUF + c2 * 32);
            unsigned Bh[8][2];
#pragma unroll
            for (int np = 0; np < 4; ++np)
                ldsm4(&Bh[2 * np][0], sBm + bo + np * (16 * BST));
#pragma unroll
            for (int n = 0; n < 8; ++n) mma_f16(acc[n], Ah, Bh[n][0], Bh[n][1]);
            mma_f16(accd, Ah, ONES, ONES);
        }
    }

    // ---- write partials ----
    if ((l & 3) == 0) {
        g_pden[split][i0 + w * 16 + rq]     = accd[0];
        g_pden[split][i0 + w * 16 + 8 + rq] = accd[2];
    }
    {
        const int row = i0 + w * 16 + rq;
        const int cq = cqi * 2;
#pragma unroll
        for (int n = 0; n < 8; ++n) {
            *(float2*)&g_pacc[split][row][n * 8 + cq]     = make_float2(acc[n][0], acc[n][1]);
            *(float2*)&g_pacc[split][row + 8][n * 8 + cq] = make_float2(acc[n][2], acc[n][3]);
        }
    }

    // ---- fused combine: last CTA of this row-tile reduces all splits ----
    __threadfence();
    __syncthreads();
    if (tid == 0)
        s_last = (atomicAdd(&g_cnt[blockIdx.x >> 3], 1) == JSPLITS - 1);
    __syncthreads();
    if (s_last) {
        __threadfence();
        for (int t = tid; t < 128 * 16; t += 256) {
            const int row = i0 + (t >> 4);
            const int c4 = (t & 15) * 4;
            float4 av2 = make_float4(0.f, 0.f, 0.f, 0.f);
            float den = 0.f;
#pragma unroll
            for (int sp = 0; sp < JSPLITS; ++sp) {
                float4 v = *(const float4*)&g_pacc[sp][row][c4];
                av2.x += v.x; av2.y += v.y; av2.z += v.z; av2.w += v.w;
                den += g_pden[sp][row];
            }
            if (den == 0.f) den = 1.f;
            float inv = 1.f / den;
            float4 o;
            o.x = av2.x * inv; o.x = o.x > 0.f ? o.x : expm1f(o.x);
            o.y = av2.y * inv; o.y = o.y > 0.f ? o.y : expm1f(o.y);
            o.z = av2.z * inv; o.z = o.z > 0.f ? o.z : expm1f(o.z);
            o.w = av2.w * inv; o.w = o.w > 0.f ? o.w : expm1f(o.w);
            *(float4*)&out[(size_t)row * NOUT + c4] = o;
        }
    }
}

// ---------------------------------------------------------------------------
extern "C" void kernel_launch(void* const* d_in, const int* in_sizes, int n_in,
                              void* d_out, int out_size) {
    const float* h   = (const float*)d_in[0];
    const float* W   = (const float*)d_in[1];
    const float* a   = (const float*)d_in[2];
    const int*   adj = (const int*)d_in[3];
    float* out = (float*)d_out;

    prep_w<<<32, 256>>>(W);
    wh_mma<<<128, 256>>>(h, a);
    e2max_kernel<<<1, 256>>>();
    attn_kernel<<<(NN / 128) * JSPLITS, 256>>>(adj, out);
}

// round 16
// speedup vs baseline: 1.5855x; 1.0406x over previous
#include <cuda_runtime.h>
#include <cuda_bf16.h>
#include <cuda_fp16.h>
#include <cstdint>

#define NN      8192
#define F_IN    512
#define NOUT    64
#define LRA     0.2f
#define L2E     1.4426950408889634f
#define JSPLITS 8
#define JLEN    (NN / JSPLITS)     // 1024
#define NCH     (JLEN / 16)        // 64 chunks of k=16
#define NBLK    (NCH / 2)          // 32 blocks of k=32
#define BST     80
#define BBUF    (64 * BST)

// ---------------- device scratch (no cudaMalloc allowed) -------------------
__device__ uint4 g_W_pk[64 * 32 * 4];
__device__ __align__(16) __half g_WhT_hi[NOUT * NN];   // j-permuted within 16-groups
__device__ float g_e1[NN];
__device__ float g_e2[NN];
__device__ unsigned g_m2u;                             // monotone-encoded max(e2)
__device__ float g_pacc[JSPLITS][NN][NOUT];
__device__ float g_pden[JSPLITS][NN];
__device__ int   g_cnt[64];

// ---------------- helpers ---------------------------------------------------
__device__ __forceinline__ void mma_bf16(float* d, const unsigned* a,
                                         unsigned b0, unsigned b1) {
    asm volatile(
        "mma.sync.aligned.m16n8k16.row.col.f32.bf16.bf16.f32 "
        "{%0,%1,%2,%3}, {%4,%5,%6,%7}, {%8,%9}, {%0,%1,%2,%3};"
        : "+f"(d[0]), "+f"(d[1]), "+f"(d[2]), "+f"(d[3])
        : "r"(a[0]), "r"(a[1]), "r"(a[2]), "r"(a[3]), "r"(b0), "r"(b1));
}
__device__ __forceinline__ void mma_f16(float* d, const unsigned* a,
                                        unsigned b0, unsigned b1) {
    asm volatile(
        "mma.sync.aligned.m16n8k16.row.col.f32.f16.f16.f32 "
        "{%0,%1,%2,%3}, {%4,%5,%6,%7}, {%8,%9}, {%0,%1,%2,%3};"
        : "+f"(d[0]), "+f"(d[1]), "+f"(d[2]), "+f"(d[3])
        : "r"(a[0]), "r"(a[1]), "r"(a[2]), "r"(a[3]), "r"(b0), "r"(b1));
}
__device__ __forceinline__ void ldsm4(unsigned* r, uint32_t addr) {
    asm volatile("ldmatrix.sync.aligned.m8n8.x4.shared.b16 {%0,%1,%2,%3}, [%4];"
                 : "=r"(r[0]), "=r"(r[1]), "=r"(r[2]), "=r"(r[3]) : "r"(addr));
}
__device__ __forceinline__ unsigned cvt2b(float po, float pe) {
    unsigned r;
    asm("cvt.rn.bf16x2.f32 %0, %1, %2;" : "=r"(r) : "f"(po), "f"(pe));
    return r;
}
__device__ __forceinline__ unsigned cvt2h(float po, float pe) {
    unsigned r;
    asm("cvt.rn.f16x2.f32 %0, %1, %2;" : "=r"(r) : "f"(po), "f"(pe));
    return r;
}
__device__ __forceinline__ unsigned ex2h2(unsigned s) {
    unsigned r;
    asm("ex2.approx.f16x2 %0, %1;" : "=r"(r) : "r"(s));
    return r;
}
__device__ __forceinline__ unsigned mulh2(unsigned a, unsigned b) {
    unsigned r;
    asm("mul.rn.f16x2 %0, %1, %2;" : "=r"(r) : "r"(a), "r"(b));
    return r;
}
__device__ __forceinline__ float bfhf(float x) {
    return __bfloat162float(__float2bfloat16_rn(x));
}
__device__ __forceinline__ uint32_t smem_u32(const void* p) {
    return (uint32_t)__cvta_generic_to_shared(p);
}
__device__ __forceinline__ void cpa16(uint32_t dst, const void* src) {
    asm volatile("cp.async.cg.shared.global [%0], [%1], 16;" :: "r"(dst), "l"(src));
}
__device__ __forceinline__ void cpcommit() {
    asm volatile("cp.async.commit_group;" ::: "memory");
}
template <int N> __device__ __forceinline__ void cpwait() {
    asm volatile("cp.async.wait_group %0;" :: "n"(N) : "memory");
}

// ---------------------------------------------------------------------------
// Kernel 0: pack W into bf16 hi/lo fragment layout + init m2/counters.
// ---------------------------------------------------------------------------
__global__ void __launch_bounds__(256) prep_w(const float* __restrict__ W) {
    const int t = blockIdx.x * 256 + threadIdx.x;
    if (t == 0) g_m2u = 0u;            // encoded -inf
    if (t < 64) g_cnt[t] = 0;
    const int s = t & 3, kc = (t >> 2) & 31, n = t >> 7;
    const int k0 = kc * 16 + 2 * s;
    float v00 = W[(k0 + 0) * 64 + n], v01 = W[(k0 + 1) * 64 + n];
    float v10 = W[(k0 + 8) * 64 + n], v11 = W[(k0 + 9) * 64 + n];
    float h00 = bfhf(v00), h01 = bfhf(v01), h10 = bfhf(v10), h11 = bfhf(v11);
    uint4 o;
    o.x = cvt2b(h01, h00);
    o.y = cvt2b(h11, h10);
    o.z = cvt2b(v01 - h01, v00 - h00);
    o.w = cvt2b(v11 - h11, v10 - h10);
    g_W_pk[(n * 32 + kc) * 4 + s] = o;
}

// ---------------------------------------------------------------------------
// Kernel 1: Wh = h @ W via mma.sync (3-product bf16 split).
// Epilogue: e1/e2 + fused atomic max(e2) + j-permuted fp16 WhT pack.
// ---------------------------------------------------------------------------
__global__ void __launch_bounds__(256, 1) wh_mma(const float* __restrict__ h,
                                                 const float* __restrict__ a) {
    __shared__ float s_h[3][64][20];
    __shared__ float s_t[64][65];
    __shared__ float s_e1p[8][16];
    __shared__ float s_e2p[8][16];

    const int tid = threadIdx.x;
    const int w = tid >> 5;
    const int l = tid & 31;
    const int wg = w >> 1;
    const int half = w & 1;
    const int r = l >> 2;
    const int c = (l & 3) * 2;
    const int node0 = blockIdx.x * 64;

    const uint32_t shb = smem_u32(&s_h[0][0][0]);
    auto stage = [&](int kc, int s) {
        const int row = tid >> 2, q4 = tid & 3;
        const float* src = h + (size_t)(node0 + row) * F_IN + kc * 16 + q4 * 4;
        cpa16(shb + (uint32_t)((s * 64 + row) * 20 + q4 * 4) * 4, src);
    };

    stage(0, 0); cpcommit();
    stage(1, 1); cpcommit();

    float acc[4][4];
#pragma unroll
    for (int n = 0; n < 4; ++n)
#pragma unroll
        for (int q = 0; q < 4; ++q) acc[n][q] = 0.f;

    const uint4* __restrict__ wpk = g_W_pk;

    for (int kc = 0; kc < 32; ++kc) {
        const int ss = kc % 3;
        if (kc + 1 < 32) cpwait<1>(); else cpwait<0>();
        __syncthreads();
        if (kc + 2 < 32) { stage(kc + 2, (kc + 2) % 3); cpcommit(); }

        uint4 B4[4];
#pragma unroll
        for (int nt = 0; nt < 4; ++nt)
            B4[nt] = wpk[(((half * 4 + nt) * 8 + r) * 32 + kc) * 4 + (l & 3)];

        float2 v0 = *(const float2*)&s_h[ss][wg * 16 + r][c];
        float2 v1 = *(const float2*)&s_h[ss][wg * 16 + r + 8][c];
        float2 v2 = *(const float2*)&s_h[ss][wg * 16 + r][c + 8];
        float2 v3 = *(const float2*)&s_h[ss][wg * 16 + r + 8][c + 8];
        float h0x = bfhf(v0.x), h0y = bfhf(v0.y);
        float h1x = bfhf(v1.x), h1y = bfhf(v1.y);
        float h2x = bfhf(v2.x), h2y = bfhf(v2.y);
        float h3x = bfhf(v3.x), h3y = bfhf(v3.y);
        unsigned Ah[4], Al[4];
        Ah[0] = cvt2b(h0y, h0x); Al[0] = cvt2b(v0.y - h0y, v0.x - h0x);
        Ah[1] = cvt2b(h1y, h1x); Al[1] = cvt2b(v1.y - h1y, v1.x - h1x);
        Ah[2] = cvt2b(h2y, h2x); Al[2] = cvt2b(v2.y - h2y, v2.x - h2x);
        Ah[3] = cvt2b(h3y, h3x); Al[3] = cvt2b(v3.y - h3y, v3.x - h3x);

#pragma unroll
        for (int nt = 0; nt < 4; ++nt) mma_bf16(acc[nt], Ah, B4[nt].x, B4[nt].y);
#pragma unroll
        for (int nt = 0; nt < 4; ++nt) mma_bf16(acc[nt], Al, B4[nt].x, B4[nt].y);
#pragma unroll
        for (int nt = 0; nt < 4; ++nt) mma_bf16(acc[nt], Ah, B4[nt].z, B4[nt].w);
    }

    {
        float e1p0 = 0.f, e1p8 = 0.f, e2p0 = 0.f, e2p8 = 0.f;
#pragma unroll
        for (int nt = 0; nt < 4; ++nt) {
            const int col = half * 32 + nt * 8 + c;
            float2 a1v = *(const float2*)&a[col];
            float2 a2v = *(const float2*)&a[NOUT + col];
            e1p0 += acc[nt][0] * a1v.x + acc[nt][1] * a1v.y;
            e1p8 += acc[nt][2] * a1v.x + acc[nt][3] * a1v.y;
            e2p0 += acc[nt][0] * a2v.x + acc[nt][1] * a2v.y;
            e2p8 += acc[nt][2] * a2v.x + acc[nt][3] * a2v.y;
        }
#pragma unroll
        for (int off = 1; off <= 2; off <<= 1) {
            e1p0 += __shfl_xor_sync(0xffffffffu, e1p0, off);
            e1p8 += __shfl_xor_sync(0xffffffffu, e1p8, off);
            e2p0 += __shfl_xor_sync(0xffffffffu, e2p0, off);
            e2p8 += __shfl_xor_sync(0xffffffffu, e2p8, off);
        }
        if ((l & 3) == 0) {
            s_e1p[w][r] = e1p0; s_e1p[w][r + 8] = e1p8;
            s_e2p[w][r] = e2p0; s_e2p[w][r + 8] = e2p8;
        }
    }

#pragma unroll
    for (int nt = 0; nt < 4; ++nt) {
        const int cb = half * 32 + nt * 8 + c;
        s_t[wg * 16 + r][cb]         = acc[nt][0];
        s_t[wg * 16 + r][cb + 1]     = acc[nt][1];
        s_t[wg * 16 + r + 8][cb]     = acc[nt][2];
        s_t[wg * 16 + r + 8][cb + 1] = acc[nt][3];
    }
    __syncthreads();

    if (tid < 64) {
        const int wg2 = tid >> 4, rr = tid & 15;
        const float e2v = s_e2p[2 * wg2][rr] + s_e2p[2 * wg2 + 1][rr];
        g_e1[node0 + wg2 * 16 + rr] = s_e1p[2 * wg2][rr] + s_e1p[2 * wg2 + 1][rr];
        g_e2[node0 + wg2 * 16 + rr] = e2v;
        // fused global max(e2): monotone encode + warp reduce + 1 atomic/warp
        unsigned enc = __float_as_uint(e2v);
        enc = (enc & 0x80000000u) ? ~enc : (enc | 0x80000000u);
#pragma unroll
        for (int off = 16; off; off >>= 1)
            enc = max(enc, __shfl_xor_sync(0xffffffffu, enc, off));
        if ((tid & 31) == 0) atomicMax(&g_m2u, enc);
    }

    // ---- pack WhT fp16 with j-permutation within the 16-group ----
    {
        const int col = tid >> 2, nh = tid & 3;
        float f[16];
#pragma unroll
        for (int j = 0; j < 16; ++j) f[j] = s_t[nh * 16 + j][col];
        unsigned hw[8];
#pragma unroll
        for (int q = 0; q < 4; ++q) {
            hw[q]     = cvt2h(f[4 * q + 1], f[4 * q]);
            hw[4 + q] = cvt2h(f[4 * q + 3], f[4 * q + 2]);
        }
        uint4* dh = (uint4*)(g_WhT_hi + (size_t)col * NN + blockIdx.x * 64 + nh * 16);
        dh[0] = *(uint4*)&hw[0];
        dh[1] = *(uint4*)&hw[4];
    }
}

// ---------------------------------------------------------------------------
// Kernel 2: fused masked-exp + fp16 GEMM + ones-GEMM den + fused combine.
// A-gen: fp32 s via lrelu-shift fold (3 ops/elem), packed ex2.approx.f16x2
// (1 MUFU/pair -> output IS the fragment), mask applied post-exp via
// IMAD-built fp16 mask (adj in {0,1}, s<=0 so ex2<=1: safe).
// ---------------------------------------------------------------------------
__global__ void __launch_bounds__(256, 2) attn_kernel(const int* __restrict__ adj,
                                                      float* __restrict__ out) {
    __shared__ float s_e2[JLEN];
    __shared__ __align__(16) char s_B[3][BBUF];
    __shared__ int s_last;

    const int tid = threadIdx.x;
    const int w = tid >> 5;
    const int l = tid & 31;
    const int i0 = (int)(blockIdx.x >> 3) * 128;
    const int split = blockIdx.x & 7;
    const int j0 = split * JLEN;

    {
        float4* d = (float4*)s_e2;
        const float4* s = (const float4*)(g_e2 + j0);
        for (int k = tid; k < JLEN / 4; k += 256) {
            float4 v = s[k];
            v.x *= L2E; v.y *= L2E; v.z *= L2E; v.w *= L2E;
            d[k] = v;
        }
    }

    const int rq = l >> 2;
    const int cqi = l & 3;
    float M2;
    {
        unsigned mu = g_m2u;
        M2 = __uint_as_float((mu & 0x80000000u) ? (mu ^ 0x80000000u) : ~mu);
    }
    const float M2s = M2 * L2E;

    float e1a[2], e1b[2];
    const int* rb[2];
#pragma unroll
    for (int k = 0; k < 2; ++k) {
        int row = i0 + w * 16 + 8 * k + rq;
        float e1r = g_e1[row] * L2E;
        float mv = e1r + M2s;
        float mi = fmaxf(mv, LRA * mv);        // row max logit (base-2)
        e1a[k] = e1r - mi;
        e1b[k] = LRA * e1r - mi;
        rb[k] = adj + (size_t)row * NN + j0 + 4 * cqi;
    }

    const uint32_t sBs = smem_u32(&s_B[0][0]);
    auto stage = [&](int blk, int s) {
        const int c = tid >> 6;
        const int n = tid & 63;
        const __half* src = g_WhT_hi + (size_t)n * NN + j0 + blk * 32 + c * 8;
        cpa16(sBs + (uint32_t)(s * BBUF + n * BST + c * 16), src);
    };

    const int g = l >> 3, lr = l & 7;
    const uint32_t sBm = sBs + (uint32_t)((lr + ((g >> 1) << 3)) * BST + ((g & 1) << 4));

    float acc[8][4];
#pragma unroll
    for (int n = 0; n < 8; ++n)
#pragma unroll
        for (int q = 0; q < 4; ++q) acc[n][q] = 0.f;
    float accd[4] = {0.f, 0.f, 0.f, 0.f};
    const unsigned ONES = 0x3C003C00u;

    // depth-2 adj register pipeline: one int4 per row per chunk
    int4 av[2][2];
    auto loadAdj = [&](int ch) {
        const int b = ch & 1;
#pragma unroll
        for (int k = 0; k < 2; ++k)
            av[b][k] = *(const int4*)(rb[k] + ch * 16);
    };

    stage(0, 0); cpcommit();
    stage(1, 1); cpcommit();
    loadAdj(0);
    loadAdj(1);

    for (int blk = 0; blk < NBLK; ++blk) {
        const int s = blk % 3;
        if (blk + 1 < NBLK) cpwait<1>(); else cpwait<0>();
        __syncthreads();
        if (blk + 2 < NBLK) { stage(blk + 2, (blk + 2) % 3); cpcommit(); }

#pragma unroll
        for (int c2 = 0; c2 < 2; ++c2) {
            const int ch = blk * 2 + c2;
            const int b = ch & 1;

            // ---- A fragments: folded lrelu-shift, packed f16x2 exp, mask ----
            const float4 e2v = *(const float4*)(s_e2 + ch * 16 + 4 * cqi);
            unsigned Ah[4];
#pragma unroll
            for (int k = 0; k < 2; ++k) {
                float s0 = fmaxf(e2v.x + e1a[k], fmaf(LRA, e2v.x, e1b[k]));
                float s1 = fmaxf(e2v.y + e1a[k], fmaf(LRA, e2v.y, e1b[k]));
                float s2 = fmaxf(e2v.z + e1a[k], fmaf(LRA, e2v.z, e1b[k]));
                float s3 = fmaxf(e2v.w + e1a[k], fmaf(LRA, e2v.w, e1b[k]));
                unsigned p0 = ex2h2(cvt2h(s1, s0));
                unsigned p1 = ex2h2(cvt2h(s3, s2));
                unsigned m0 = (unsigned)av[b][k].x * 0x3C00u
                            + (unsigned)av[b][k].y * 0x3C000000u;
                unsigned m1 = (unsigned)av[b][k].z * 0x3C00u
                            + (unsigned)av[b][k].w * 0x3C000000u;
                Ah[k]     = mulh2(p0, m0);
                Ah[k + 2] = mulh2(p1, m1);
            }

            // ---- refill this buffer for chunk ch+2 ----
            if (ch + 2 < NCH) loadAdj(ch + 2);

            // ---- B fragments + products (+ ones-GEMM denominator) ----
            const uint32_t bo = (uint32_t)(s * BBUF + c2 * 32);
            unsigned Bh[8][2];
#pragma unroll
            for (int np = 0; np < 4; ++np)
                ldsm4(&Bh[2 * np][0], sBm + bo + np * (16 * BST));
#pragma unroll
            for (int n = 0; n < 8; ++n) mma_f16(acc[n], Ah, Bh[n][0], Bh[n][1]);
            mma_f16(accd, Ah, ONES, ONES);
        }
    }

    // ---- write partials ----
    if ((l & 3) == 0) {
        g_pden[split][i0 + w * 16 + rq]     = accd[0];
        g_pden[split][i0 + w * 16 + 8 + rq] = accd[2];
    }
    {
        const int row = i0 + w * 16 + rq;
        const int cq = cqi * 2;
#pragma unroll
        for (int n = 0; n < 8; ++n) {
            *(float2*)&g_pacc[split][row][n * 8 + cq]     = make_float2(acc[n][0], acc[n][1]);
            *(float2*)&g_pacc[split][row + 8][n * 8 + cq] = make_float2(acc[n][2], acc[n][3]);
        }
    }

    // ---- fused combine: last CTA of this row-tile reduces all splits ----
    __threadfence();
    __syncthreads();
    if (tid == 0)
        s_last = (atomicAdd(&g_cnt[blockIdx.x >> 3], 1) == JSPLITS - 1);
    __syncthreads();
    if (s_last) {
        __threadfence();
        for (int t = tid; t < 128 * 16; t += 256) {
            const int row = i0 + (t >> 4);
            const int c4 = (t & 15) * 4;
            float4 av2 = make_float4(0.f, 0.f, 0.f, 0.f);
            float den = 0.f;
#pragma unroll
            for (int sp = 0; sp < JSPLITS; ++sp) {
                float4 v = *(const float4*)&g_pacc[sp][row][c4];
                av2.x += v.x; av2.y += v.y; av2.z += v.z; av2.w += v.w;
                den += g_pden[sp][row];
            }
            if (den == 0.f) den = 1.f;
            float inv = 1.f / den;
            float4 o;
            o.x = av2.x * inv; o.x = o.x > 0.f ? o.x : expm1f(o.x);
            o.y = av2.y * inv; o.y = o.y > 0.f ? o.y : expm1f(o.y);
            o.z = av2.z * inv; o.z = o.z > 0.f ? o.z : expm1f(o.z);
            o.w = av2.w * inv; o.w = o.w > 0.f ? o.w : expm1f(o.w);
            *(float4*)&out[(size_t)row * NOUT + c4] = o;
        }
    }
}

// ---------------------------------------------------------------------------
extern "C" void kernel_launch(void* const* d_in, const int* in_sizes, int n_in,
                              void* d_out, int out_size) {
    const float* h   = (const float*)d_in[0];
    const float* W   = (const float*)d_in[1];
    const float* a   = (const float*)d_in[2];
    const int*   adj = (const int*)d_in[3];
    float* out = (float*)d_out;

    prep_w<<<32, 256>>>(W);
    wh_mma<<<128, 256>>>(h, a);
    attn_kernel<<<(NN / 128) * JSPLITS, 256>>>(adj, out);
}

// round 17
// speedup vs baseline: 1.8476x; 1.1653x over previous
#include <cuda_runtime.h>
#include <cuda_bf16.h>
#include <cuda_fp16.h>
#include <cstdint>

#define NN      8192
#define F_IN    512
#define NOUT    64
#define LRA     0.2f
#define L2E     1.4426950408889634f
#define JSPLITS 4
#define JLEN    (NN / JSPLITS)     // 2048
#define NCH     (JLEN / 16)        // 128 chunks of k=16
#define NBLK    (NCH / 4)          // 32 blocks of k=64
#define BST     144                // 128B data + 16B pad per n-row
#define BBUF    (64 * BST)         // 9216 B per stage

// ---------------- device scratch (no cudaMalloc allowed) -------------------
__device__ uint4 g_W_pk[64 * 32 * 4];
__device__ __align__(16) __half g_WhT_hi[NOUT * NN];   // j-permuted within 16-groups
__device__ float g_e1[NN];
__device__ float g_e2[NN];
__device__ unsigned g_m2u;                             // monotone-encoded max(e2)
__device__ float g_pacc[JSPLITS][NN][NOUT];
__device__ float g_pden[JSPLITS][NN];
__device__ int   g_cnt[64];

// ---------------- helpers ---------------------------------------------------
__device__ __forceinline__ void mma_bf16(float* d, const unsigned* a,
                                         unsigned b0, unsigned b1) {
    asm volatile(
        "mma.sync.aligned.m16n8k16.row.col.f32.bf16.bf16.f32 "
        "{%0,%1,%2,%3}, {%4,%5,%6,%7}, {%8,%9}, {%0,%1,%2,%3};"
        : "+f"(d[0]), "+f"(d[1]), "+f"(d[2]), "+f"(d[3])
        : "r"(a[0]), "r"(a[1]), "r"(a[2]), "r"(a[3]), "r"(b0), "r"(b1));
}
__device__ __forceinline__ void mma_f16(float* d, const unsigned* a,
                                        unsigned b0, unsigned b1) {
    asm volatile(
        "mma.sync.aligned.m16n8k16.row.col.f32.f16.f16.f32 "
        "{%0,%1,%2,%3}, {%4,%5,%6,%7}, {%8,%9}, {%0,%1,%2,%3};"
        : "+f"(d[0]), "+f"(d[1]), "+f"(d[2]), "+f"(d[3])
        : "r"(a[0]), "r"(a[1]), "r"(a[2]), "r"(a[3]), "r"(b0), "r"(b1));
}
__device__ __forceinline__ void ldsm4(unsigned* r, uint32_t addr) {
    asm volatile("ldmatrix.sync.aligned.m8n8.x4.shared.b16 {%0,%1,%2,%3}, [%4];"
                 : "=r"(r[0]), "=r"(r[1]), "=r"(r[2]), "=r"(r[3]) : "r"(addr));
}
__device__ __forceinline__ unsigned cvt2b(float po, float pe) {
    unsigned r;
    asm("cvt.rn.bf16x2.f32 %0, %1, %2;" : "=r"(r) : "f"(po), "f"(pe));
    return r;
}
__device__ __forceinline__ unsigned cvt2h(float po, float pe) {
    unsigned r;
    asm("cvt.rn.f16x2.f32 %0, %1, %2;" : "=r"(r) : "f"(po), "f"(pe));
    return r;
}
__device__ __forceinline__ unsigned ex2h2(unsigned s) {
    unsigned r;
    asm("ex2.approx.f16x2 %0, %1;" : "=r"(r) : "r"(s));
    return r;
}
__device__ __forceinline__ unsigned mulh2(unsigned a, unsigned b) {
    unsigned r;
    asm("mul.rn.f16x2 %0, %1, %2;" : "=r"(r) : "r"(a), "r"(b));
    return r;
}
__device__ __forceinline__ float bfhf(float x) {
    return __bfloat162float(__float2bfloat16_rn(x));
}
__device__ __forceinline__ uint32_t smem_u32(const void* p) {
    return (uint32_t)__cvta_generic_to_shared(p);
}
__device__ __forceinline__ void cpa16(uint32_t dst, const void* src) {
    asm volatile("cp.async.cg.shared.global [%0], [%1], 16;" :: "r"(dst), "l"(src));
}
__device__ __forceinline__ void cpcommit() {
    asm volatile("cp.async.commit_group;" ::: "memory");
}
template <int N> __device__ __forceinline__ void cpwait() {
    asm volatile("cp.async.wait_group %0;" :: "n"(N) : "memory");
}

// ---------------------------------------------------------------------------
// Kernel 0: pack W (coalesced through smem). One CTA per kc (grid 32).
// ---------------------------------------------------------------------------
__global__ void __launch_bounds__(256) prep_w(const float* __restrict__ W) {
    __shared__ float sw[16][64];
    const int tid = threadIdx.x;
    const int kc = blockIdx.x;

    // coalesced load: 16 rows x 64 cols fp32 (4 KB)
    {
        const int r = tid >> 4, cb = tid & 15;
        *(float4*)&sw[r][cb * 4] =
            *(const float4*)&W[(size_t)(kc * 16 + r) * 64 + cb * 4];
    }
    if (blockIdx.x == 0) {
        if (tid == 0) g_m2u = 0u;
        if (tid < 64) g_cnt[tid] = 0;
    }
    __syncthreads();

    const int s = tid & 3, n = tid >> 2;
    float v00 = sw[2 * s][n],     v01 = sw[2 * s + 1][n];
    float v10 = sw[2 * s + 8][n], v11 = sw[2 * s + 9][n];
    float h00 = bfhf(v00), h01 = bfhf(v01), h10 = bfhf(v10), h11 = bfhf(v11);
    uint4 o;
    o.x = cvt2b(h01, h00);
    o.y = cvt2b(h11, h10);
    o.z = cvt2b(v01 - h01, v00 - h00);
    o.w = cvt2b(v11 - h11, v10 - h10);
    g_W_pk[(n * 32 + kc) * 4 + s] = o;
}

// ---------------------------------------------------------------------------
// Kernel 1: Wh = h @ W via mma.sync (3-product bf16 split).
// Epilogue: e1/e2 + fused atomic max(e2) + j-permuted fp16 WhT pack.
// ---------------------------------------------------------------------------
__global__ void __launch_bounds__(256, 1) wh_mma(const float* __restrict__ h,
                                                 const float* __restrict__ a) {
    __shared__ float s_h[3][64][20];
    __shared__ float s_t[64][65];
    __shared__ float s_e1p[8][16];
    __shared__ float s_e2p[8][16];

    const int tid = threadIdx.x;
    const int w = tid >> 5;
    const int l = tid & 31;
    const int wg = w >> 1;
    const int half = w & 1;
    const int r = l >> 2;
    const int c = (l & 3) * 2;
    const int node0 = blockIdx.x * 64;

    const uint32_t shb = smem_u32(&s_h[0][0][0]);
    auto stage = [&](int kc, int s) {
        const int row = tid >> 2, q4 = tid & 3;
        const float* src = h + (size_t)(node0 + row) * F_IN + kc * 16 + q4 * 4;
        cpa16(shb + (uint32_t)((s * 64 + row) * 20 + q4 * 4) * 4, src);
    };

    stage(0, 0); cpcommit();
    stage(1, 1); cpcommit();

    float acc[4][4];
#pragma unroll
    for (int n = 0; n < 4; ++n)
#pragma unroll
        for (int q = 0; q < 4; ++q) acc[n][q] = 0.f;

    const uint4* __restrict__ wpk = g_W_pk;

    for (int kc = 0; kc < 32; ++kc) {
        const int ss = kc % 3;
        if (kc + 1 < 32) cpwait<1>(); else cpwait<0>();
        __syncthreads();
        if (kc + 2 < 32) { stage(kc + 2, (kc + 2) % 3); cpcommit(); }

        uint4 B4[4];
#pragma unroll
        for (int nt = 0; nt < 4; ++nt)
            B4[nt] = wpk[(((half * 4 + nt) * 8 + r) * 32 + kc) * 4 + (l & 3)];

        float2 v0 = *(const float2*)&s_h[ss][wg * 16 + r][c];
        float2 v1 = *(const float2*)&s_h[ss][wg * 16 + r + 8][c];
        float2 v2 = *(const float2*)&s_h[ss][wg * 16 + r][c + 8];
        float2 v3 = *(const float2*)&s_h[ss][wg * 16 + r + 8][c + 8];
        float h0x = bfhf(v0.x), h0y = bfhf(v0.y);
        float h1x = bfhf(v1.x), h1y = bfhf(v1.y);
        float h2x = bfhf(v2.x), h2y = bfhf(v2.y);
        float h3x = bfhf(v3.x), h3y = bfhf(v3.y);
        unsigned Ah[4], Al[4];
        Ah[0] = cvt2b(h0y, h0x); Al[0] = cvt2b(v0.y - h0y, v0.x - h0x);
        Ah[1] = cvt2b(h1y, h1x); Al[1] = cvt2b(v1.y - h1y, v1.x - h1x);
        Ah[2] = cvt2b(h2y, h2x); Al[2] = cvt2b(v2.y - h2y, v2.x - h2x);
        Ah[3] = cvt2b(h3y, h3x); Al[3] = cvt2b(v3.y - h3y, v3.x - h3x);

#pragma unroll
        for (int nt = 0; nt < 4; ++nt) mma_bf16(acc[nt], Ah, B4[nt].x, B4[nt].y);
#pragma unroll
        for (int nt = 0; nt < 4; ++nt) mma_bf16(acc[nt], Al, B4[nt].x, B4[nt].y);
#pragma unroll
        for (int nt = 0; nt < 4; ++nt) mma_bf16(acc[nt], Ah, B4[nt].z, B4[nt].w);
    }

    {
        float e1p0 = 0.f, e1p8 = 0.f, e2p0 = 0.f, e2p8 = 0.f;
#pragma unroll
        for (int nt = 0; nt < 4; ++nt) {
            const int col = half * 32 + nt * 8 + c;
            float2 a1v = *(const float2*)&a[col];
            float2 a2v = *(const float2*)&a[NOUT + col];
            e1p0 += acc[nt][0] * a1v.x + acc[nt][1] * a1v.y;
            e1p8 += acc[nt][2] * a1v.x + acc[nt][3] * a1v.y;
            e2p0 += acc[nt][0] * a2v.x + acc[nt][1] * a2v.y;
            e2p8 += acc[nt][2] * a2v.x + acc[nt][3] * a2v.y;
        }
#pragma unroll
        for (int off = 1; off <= 2; off <<= 1) {
            e1p0 += __shfl_xor_sync(0xffffffffu, e1p0, off);
            e1p8 += __shfl_xor_sync(0xffffffffu, e1p8, off);
            e2p0 += __shfl_xor_sync(0xffffffffu, e2p0, off);
            e2p8 += __shfl_xor_sync(0xffffffffu, e2p8, off);
        }
        if ((l & 3) == 0) {
            s_e1p[w][r] = e1p0; s_e1p[w][r + 8] = e1p8;
            s_e2p[w][r] = e2p0; s_e2p[w][r + 8] = e2p8;
        }
    }

#pragma unroll
    for (int nt = 0; nt < 4; ++nt) {
        const int cb = half * 32 + nt * 8 + c;
        s_t[wg * 16 + r][cb]         = acc[nt][0];
        s_t[wg * 16 + r][cb + 1]     = acc[nt][1];
        s_t[wg * 16 + r + 8][cb]     = acc[nt][2];
        s_t[wg * 16 + r + 8][cb + 1] = acc[nt][3];
    }
    __syncthreads();

    if (tid < 64) {
        const int wg2 = tid >> 4, rr = tid & 15;
        const float e2v = s_e2p[2 * wg2][rr] + s_e2p[2 * wg2 + 1][rr];
        g_e1[node0 + wg2 * 16 + rr] = s_e1p[2 * wg2][rr] + s_e1p[2 * wg2 + 1][rr];
        g_e2[node0 + wg2 * 16 + rr] = e2v;
        unsigned enc = __float_as_uint(e2v);
        enc = (enc & 0x80000000u) ? ~enc : (enc | 0x80000000u);
#pragma unroll
        for (int off = 16; off; off >>= 1)
            enc = max(enc, __shfl_xor_sync(0xffffffffu, enc, off));
        if ((tid & 31) == 0) atomicMax(&g_m2u, enc);
    }

    {
        const int col = tid >> 2, nh = tid & 3;
        float f[16];
#pragma unroll
        for (int j = 0; j < 16; ++j) f[j] = s_t[nh * 16 + j][col];
        unsigned hw[8];
#pragma unroll
        for (int q = 0; q < 4; ++q) {
            hw[q]     = cvt2h(f[4 * q + 1], f[4 * q]);
            hw[4 + q] = cvt2h(f[4 * q + 3], f[4 * q + 2]);
        }
        uint4* dh = (uint4*)(g_WhT_hi + (size_t)col * NN + blockIdx.x * 64 + nh * 16);
        dh[0] = *(uint4*)&hw[0];
        dh[1] = *(uint4*)&hw[4];
    }
}

// ---------------------------------------------------------------------------
// Kernel 2: fused masked-exp + fp16 GEMM + ones-GEMM den + fused combine.
// k=64 pipeline stages (16 fewer barrier convoys), adj depth-4 register
// pipeline (static buffer index = c2), JSPLITS=4 -> grid 256 = one wave.
// ---------------------------------------------------------------------------
__global__ void __launch_bounds__(256, 2) attn_kernel(const int* __restrict__ adj,
                                                      float* __restrict__ out) {
    __shared__ float s_e2[JLEN];                 // 8 KB
    __shared__ __align__(16) char s_B[3][BBUF];  // 27 KB
    __shared__ int s_last;

    const int tid = threadIdx.x;
    const int w = tid >> 5;
    const int l = tid & 31;
    const int i0 = (int)(blockIdx.x >> 2) * 128;
    const int split = blockIdx.x & 3;
    const int j0 = split * JLEN;

    {
        float4* d = (float4*)s_e2;
        const float4* s = (const float4*)(g_e2 + j0);
        for (int k = tid; k < JLEN / 4; k += 256) {
            float4 v = s[k];
            v.x *= L2E; v.y *= L2E; v.z *= L2E; v.w *= L2E;
            d[k] = v;
        }
    }

    const int rq = l >> 2;
    const int cqi = l & 3;
    float M2;
    {
        unsigned mu = g_m2u;
        M2 = __uint_as_float((mu & 0x80000000u) ? (mu ^ 0x80000000u) : ~mu);
    }
    const float M2s = M2 * L2E;

    float e1a[2], e1b[2];
    const int* rb[2];
#pragma unroll
    for (int k = 0; k < 2; ++k) {
        int row = i0 + w * 16 + 8 * k + rq;
        float e1r = g_e1[row] * L2E;
        float mv = e1r + M2s;
        float mi = fmaxf(mv, LRA * mv);
        e1a[k] = e1r - mi;
        e1b[k] = LRA * e1r - mi;
        rb[k] = adj + (size_t)row * NN + j0 + 4 * cqi;
    }

    const uint32_t sBs = smem_u32(&s_B[0][0]);
    // B tile for block blk: 64n x 64k fp16 = 8 KB = two cpa16 per thread
    auto stage = [&](int blk, int s) {
#pragma unroll
        for (int it = 0; it < 2; ++it) {
            const int idx = it * 256 + tid;      // 0..511
            const int c = idx >> 6;              // 16B chunk 0..7
            const int n = idx & 63;              // n-row
            const __half* src = g_WhT_hi + (size_t)n * NN + j0 + blk * 64 + c * 8;
            cpa16(sBs + (uint32_t)(s * BBUF + n * BST + c * 16), src);
        }
    };

    const int g = l >> 3, lr = l & 7;
    const uint32_t sBm = sBs + (uint32_t)((lr + ((g >> 1) << 3)) * BST + ((g & 1) << 4));

    float acc[8][4];
#pragma unroll
    for (int n = 0; n < 8; ++n)
#pragma unroll
        for (int q = 0; q < 4; ++q) acc[n][q] = 0.f;
    float accd[4] = {0.f, 0.f, 0.f, 0.f};
    const unsigned ONES = 0x3C003C00u;

    // depth-4 adj register pipeline: buffer index = ch & 3 (static per c2)
    int4 av[4][2];
    auto loadAdj = [&](int ch, int b) {
#pragma unroll
        for (int k = 0; k < 2; ++k)
            av[b][k] = *(const int4*)(rb[k] + ch * 16);
    };

    stage(0, 0); cpcommit();
    stage(1, 1); cpcommit();
#pragma unroll
    for (int q = 0; q < 4; ++q) loadAdj(q, q);

    for (int blk = 0; blk < NBLK; ++blk) {
        const int s = blk % 3;
        if (blk + 1 < NBLK) cpwait<1>(); else cpwait<0>();
        __syncthreads();
        if (blk + 2 < NBLK) { stage(blk + 2, (blk + 2) % 3); cpcommit(); }

#pragma unroll
        for (int c2 = 0; c2 < 4; ++c2) {
            const int ch = blk * 4 + c2;

            // ---- A fragments: folded lrelu-shift, packed f16x2 exp, mask ----
            const float4 e2v = *(const float4*)(s_e2 + ch * 16 + 4 * cqi);
            unsigned Ah[4];
#pragma unroll
            for (int k = 0; k < 2; ++k) {
                float s0 = fmaxf(e2v.x + e1a[k], fmaf(LRA, e2v.x, e1b[k]));
                float s1 = fmaxf(e2v.y + e1a[k], fmaf(LRA, e2v.y, e1b[k]));
                float s2 = fmaxf(e2v.z + e1a[k], fmaf(LRA, e2v.z, e1b[k]));
                float s3 = fmaxf(e2v.w + e1a[k], fmaf(LRA, e2v.w, e1b[k]));
                unsigned p0 = ex2h2(cvt2h(s1, s0));
                unsigned p1 = ex2h2(cvt2h(s3, s2));
                unsigned m0 = (unsigned)av[c2][k].x * 0x3C00u
                            + (unsigned)av[c2][k].y * 0x3C000000u;
                unsigned m1 = (unsigned)av[c2][k].z * 0x3C00u
                            + (unsigned)av[c2][k].w * 0x3C000000u;
                Ah[k]     = mulh2(p0, m0);
                Ah[k + 2] = mulh2(p1, m1);
            }

            // ---- refill buffer c2 with chunk ch+4 (4-chunk window) ----
            if (ch + 4 < NCH) loadAdj(ch + 4, c2);

            // ---- B fragments + products (+ ones-GEMM denominator) ----
            const uint32_t bo = (uint32_t)(s * BBUF + c2 * 32);
            unsigned Bh[8][2];
#pragma unroll
            for (int np = 0; np < 4; ++np)
                ldsm4(&Bh[2 * np][0], sBm + bo + np * (16 * BST));
#pragma unroll
            for (int n = 0; n < 8; ++n) mma_f16(acc[n], Ah, Bh[n][0], Bh[n][1]);
            mma_f16(accd, Ah, ONES, ONES);
        }
    }

    // ---- write partials ----
    if ((l & 3) == 0) {
        g_pden[split][i0 + w * 16 + rq]     = accd[0];
        g_pden[split][i0 + w * 16 + 8 + rq] = accd[2];
    }
    {
        const int row = i0 + w * 16 + rq;
        const int cq = cqi * 2;
#pragma unroll
        for (int n = 0; n < 8; ++n) {
            *(float2*)&g_pacc[split][row][n * 8 + cq]     = make_float2(acc[n][0], acc[n][1]);
            *(float2*)&g_pacc[split][row + 8][n * 8 + cq] = make_float2(acc[n][2], acc[n][3]);
        }
    }

    // ---- fused combine: last CTA of this row-tile reduces all splits ----
    __threadfence();
    __syncthreads();
    if (tid == 0)
        s_last = (atomicAdd(&g_cnt[blockIdx.x >> 2], 1) == JSPLITS - 1);
    __syncthreads();
    if (s_last) {
        __threadfence();
        for (int t = tid; t < 128 * 16; t += 256) {
            const int row = i0 + (t >> 4);
            const int c4 = (t & 15) * 4;
            float4 av2 = make_float4(0.f, 0.f, 0.f, 0.f);
            float den = 0.f;
#pragma unroll
            for (int sp = 0; sp < JSPLITS; ++sp) {
                float4 v = *(const float4*)&g_pacc[sp][row][c4];
                av2.x += v.x; av2.y += v.y; av2.z += v.z; av2.w += v.w;
                den += g_pden[sp][row];
            }
            if (den == 0.f) den = 1.f;
            float inv = 1.f / den;
            float4 o;
            o.x = av2.x * inv; o.x = o.x > 0.f ? o.x : expm1f(o.x);
            o.y = av2.y * inv; o.y = o.y > 0.f ? o.y : expm1f(o.y);
            o.z = av2.z * inv; o.z = o.z > 0.f ? o.z : expm1f(o.z);
            o.w = av2.w * inv; o.w = o.w > 0.f ? o.w : expm1f(o.w);
            *(float4*)&out[(size_t)row * NOUT + c4] = o;
        }
    }
}

// ---------------------------------------------------------------------------
extern "C" void kernel_launch(void* const* d_in, const int* in_sizes, int n_in,
                              void* d_out, int out_size) {
    const float* h   = (const float*)d_in[0];
    const float* W   = (const float*)d_in[1];
    const float* a   = (const float*)d_in[2];
    const int*   adj = (const int*)d_in[3];
    float* out = (float*)d_out;

    prep_w<<<32, 256>>>(W);
    wh_mma<<<128, 256>>>(h, a);
    attn_kernel<<<(NN / 128) * JSPLITS, 256>>>(adj, out);
}